// round 7
// baseline (speedup 1.0000x reference)
#include <cuda_runtime.h>
#include <cstdint>

// PointPillarsBEV R7.
// R6: striping was neutral. Root causes: reg-limited occupancy (52 regs, 40 of them
// duplicated packed weights -> 4 blk/SM, occ 43%) and ~12.5M issued instrs/stage
// (pack/unpack movs + scalar max merges). Fix:
//  - warp-PAIR per pillar: warp handles 32 channels (lane = 1 channel, dup-packed
//    weight = 20 regs). Per-thread fma2 halves; warps double; occ should ~2x.
//  - shared points read directly as ulonglong2 (no float4->u64 repack movs).
//  - stripe: odd bids < 6000 are PFN (3000), rest expand (4096) -> every wave mixed.

#define BEV_W 512
#define NPILLARS 12000
#define NPTS 32
#define DIN 10
#define CCH 64
#define HW 262144
#define PPB 4                         // pillars per 256-thread block (2 warps each)
#define NPFN (NPILLARS / PPB)         // 3000 pfn blocks per batch
#define NEXP 4096
#define STRIPED_GRID 7096             // 3000 pfn (odd, <6000) + 4096 expand

__device__ float g_acc[(size_t)4 * HW * CCH];   // 268MB staging (touched lines only)
__device__ unsigned char g_flag[4 * HW];        // 1MB

__device__ __forceinline__ uint64_t pack2(float lo, float hi) {
    uint64_t r; asm("mov.b64 %0, {%1, %2};" : "=l"(r) : "f"(lo), "f"(hi)); return r;
}
__device__ __forceinline__ void unpack2(uint64_t v, float& lo, float& hi) {
    asm("mov.b64 {%0, %1}, %2;" : "=f"(lo), "=f"(hi) : "l"(v));
}
__device__ __forceinline__ uint64_t fma2(uint64_t a, uint64_t b, uint64_t c) {
    uint64_t d; asm("fma.rn.f32x2 %0, %1, %2, %3;" : "=l"(d) : "l"(a), "l"(b), "l"(c)); return d;
}

// ---------------- prep: zero flags + zero touched acc cells ----------------
__global__ __launch_bounds__(256) void prep_kernel(const int* __restrict__ coords) {
    if (blockIdx.x < 256) {
        ((uint4*)g_flag)[blockIdx.x * 256 + threadIdx.x] = make_uint4(0, 0, 0, 0);
    } else {
        const int warp = threadIdx.x >> 5, lane = threadIdx.x & 31;
        const int pidx = (blockIdx.x - 256) * 8 + warp;        // [0, 48000)
        const int b = pidx / NPILLARS;
        const int y = __ldg(&coords[(size_t)pidx * 2 + 0]);
        const int x = __ldg(&coords[(size_t)pidx * 2 + 1]);
        const size_t base = ((size_t)(b * HW) + y * BEV_W + x) * CCH;
        ((float2*)(g_acc + base))[lane] = make_float2(0.f, 0.f);
    }
}

// ---------------- PFN: warp-pair per pillar, lane = 1 channel ----------------
__device__ __forceinline__ void do_pfn(
    const float* __restrict__ pillars, const int* __restrict__ coords,
    const float* __restrict__ w, const float* __restrict__ bias,
    int batch, int pfnBlk)
{
    const int wid = threadIdx.x >> 5, lane = threadIdx.x & 31;
    const int pil = wid >> 1;                  // 0..3: pillar within block
    const int h   = wid & 1;                   // channel half
    const int p   = pfnBlk * PPB + pil;
    const int c   = h * 32 + lane;             // this thread's channel

    __shared__ __align__(16) float s_pts[PPB][DIN][NPTS];   // dim-major

    if (h == 0) {   // even warp stages its pillar's points (lane = point)
        const float2* src2 = (const float2*)(pillars +
            ((size_t)(batch * NPILLARS + p) * NPTS + lane) * DIN);
        float v[DIN];
        #pragma unroll
        for (int i = 0; i < 5; i++) { float2 t = src2[i]; v[2*i] = t.x; v[2*i+1] = t.y; }
        #pragma unroll
        for (int d = 0; d < DIN; d++) s_pts[pil][d][lane] = v[d];
    }

    uint64_t wd[DIN];                          // dup-packed weights: 20 regs
    #pragma unroll
    for (int d = 0; d < DIN; d++) {
        float wv = w[d * CCH + c];
        wd[d] = pack2(wv, wv);
    }
    const float bv = bias[c];
    const uint64_t b2 = pack2(bv, bv);

    __syncthreads();

    float m = 0.f;                             // relu >= 0 -> 0-init exact
    #pragma unroll
    for (int k = 0; k < NPTS / 8; k++) {       // 8 points per iter, 4 pair-chains
        uint64_t s0 = b2, s1 = b2, s2 = b2, s3 = b2;
        #pragma unroll
        for (int d = 0; d < DIN; d++) {
            // LDS.128 broadcast: 4 consecutive points at dim d, as 2 ready u64 pairs
            const ulonglong2 A = *reinterpret_cast<const ulonglong2*>(&s_pts[pil][d][8*k]);
            const ulonglong2 B = *reinterpret_cast<const ulonglong2*>(&s_pts[pil][d][8*k+4]);
            s0 = fma2(A.x, wd[d], s0);
            s1 = fma2(A.y, wd[d], s1);
            s2 = fma2(B.x, wd[d], s2);
            s3 = fma2(B.y, wd[d], s3);
        }
        float lo, hi;
        unpack2(s0, lo, hi); m = fmaxf(m, fmaxf(lo, hi));
        unpack2(s1, lo, hi); m = fmaxf(m, fmaxf(lo, hi));
        unpack2(s2, lo, hi); m = fmaxf(m, fmaxf(lo, hi));
        unpack2(s3, lo, hi); m = fmaxf(m, fmaxf(lo, hi));
    }

    const int y = __ldg(&coords[(size_t)(batch * NPILLARS + p) * 2 + 0]);
    const int x = __ldg(&coords[(size_t)(batch * NPILLARS + p) * 2 + 1]);
    const int cell = batch * HW + y * BEV_W + x;
    if (h == 0 && lane == 0) g_flag[cell] = 1;
    atomicAdd(g_acc + (size_t)cell * CCH + c, m);   // 256B contiguous burst per pillar
}

// ---------------- expand one chunk: 1 flag load -> 4 channel stores ----------------
__device__ __forceinline__ void do_expand(float* __restrict__ out, int eb, int chunk) {
    const int t = chunk * 256 + threadIdx.x;   // [0, 1,048,576)
    const int g = t & 65535;                   // cell-group (4 cells)
    const int cb = t >> 16;                    // channel base (0..15)
    const int cell = g << 2;

    const unsigned char* fl = g_flag + eb * HW;
    const float* ab = g_acc + (size_t)eb * HW * CCH;
    float4* dst = (float4*)(out + (size_t)eb * CCH * HW);

    const uchar4 f4 = *(const uchar4*)(fl + cell);
    const bool any = (f4.x | f4.y | f4.z | f4.w) != 0;

    #pragma unroll
    for (int k = 0; k < 4; k++) {
        const int c = cb + 16 * k;
        float4 val = make_float4(0.f, 0.f, 0.f, 0.f);
        if (any) {
            if (f4.x) val.x = ab[(size_t)(cell + 0) * CCH + c];
            if (f4.y) val.y = ab[(size_t)(cell + 1) * CCH + c];
            if (f4.z) val.z = ab[(size_t)(cell + 2) * CCH + c];
            if (f4.w) val.w = ab[(size_t)(cell + 3) * CCH + c];
        }
        dst[c * (HW / 4) + g] = val;           // coalesced across consecutive g
    }
}

// ---------------- pipeline stage ----------------
__global__ __launch_bounds__(256) void stage_kernel(
    const float* __restrict__ pillars, const int* __restrict__ coords,
    const float* __restrict__ w, const float* __restrict__ bias,
    float* __restrict__ out, int pfn_batch, int exp_batch)
{
    const int bid = blockIdx.x;
    if (pfn_batch >= 0 && exp_batch >= 0) {
        // stripe: odd bids < 6000 -> pfn (3000); the rest -> expand (4096)
        if ((bid & 1) && bid < 6000) {
            do_pfn(pillars, coords, w, bias, pfn_batch, bid >> 1);
        } else {
            const int eid = (bid < 6000) ? (bid >> 1) : (bid - 3000);
            do_expand(out, exp_batch, eid);
        }
    } else if (pfn_batch >= 0) {
        do_pfn(pillars, coords, w, bias, pfn_batch, bid);
    } else {
        do_expand(out, exp_batch, bid);
    }
}

extern "C" void kernel_launch(void* const* d_in, const int* in_sizes, int n_in,
                              void* d_out, int out_size) {
    const float* pillars = (const float*)d_in[0];
    const int*   coords  = (const int*)d_in[1];
    const float* pfn_w   = (const float*)d_in[2];
    const float* pfn_b   = (const float*)d_in[3];
    float* out = (float*)d_out;

    prep_kernel<<<256 + 6000, 256>>>(coords);
    stage_kernel<<<NPFN, 256>>>(pillars, coords, pfn_w, pfn_b, out, 0, -1);
    stage_kernel<<<STRIPED_GRID, 256>>>(pillars, coords, pfn_w, pfn_b, out, 1, 0);
    stage_kernel<<<STRIPED_GRID, 256>>>(pillars, coords, pfn_w, pfn_b, out, 2, 1);
    stage_kernel<<<STRIPED_GRID, 256>>>(pillars, coords, pfn_w, pfn_b, out, 3, 2);
    stage_kernel<<<NEXP, 256>>>(pillars, coords, pfn_w, pfn_b, out, -1, 3);
}